// round 5
// baseline (speedup 1.0000x reference)
#include <cuda_runtime.h>
#include <cuda_fp16.h>
#include <cstdint>

// ============================================================================
// simpleRQA: out[n] = any_m( cos_sim(Ex[n], Ey[m]) > 0.9 )
// Ex, Ey: [8192, 1024] fp32.  out: [8192] fp32 (0.0 / 1.0)
//
// K1: normalize rows (fp32 norm, clamp 1e-8) -> fp16 scratch; zero out[].
// K2: fp16 mma.sync GEMM with fp16 accumulate (CTA tile 128x128, BK=64,
//     3-stage cp.async) fused with threshold (>0.9) + any-over-N reduce.
// ============================================================================

#define NROWS   8192
#define DIMS    1024
#define BM_     128
#define BN_     128
#define BK_     64                  // fp16 per K chunk (128 bytes/row)
#define NCHUNK  (DIMS / BK_)        // 16
#define STAGES  3
#define GT_     256                 // threads per GEMM CTA (8 warps: 4M x 2N)

#define STAGE_BYTES   (BM_ * 128 + BN_ * 128)   // 32 KB (A 16K + B 16K)
#define SMEM_DYN      (STAGES * STAGE_BYTES + 1024)

// Normalized fp16 operands (static device scratch; 16 MB each), 16B-aligned.
static __device__ uint4 g_Xb4[(size_t)NROWS * DIMS / 8];
static __device__ uint4 g_Yb4[(size_t)NROWS * DIMS / 8];

// ---------------------------------------------------------------------------
// helpers
// ---------------------------------------------------------------------------
static __device__ __forceinline__ uint32_t smem_u32(const void* p) {
    uint32_t a;
    asm("{ .reg .u64 t; cvta.to.shared.u64 t, %1; cvt.u32.u64 %0, t; }"
        : "=r"(a) : "l"(p));
    return a;
}

static __device__ __forceinline__ void cp_async16(uint32_t dst, const void* src) {
    asm volatile("cp.async.cg.shared.global [%0], [%1], 16;"
                 :: "r"(dst), "l"(src) : "memory");
}
#define CP_COMMIT() asm volatile("cp.async.commit_group;" ::: "memory")
#define CP_WAIT(n)  asm volatile("cp.async.wait_group %0;" :: "n"(n) : "memory")

static __device__ __forceinline__ void ldmatrix_x4(
    uint32_t& r0, uint32_t& r1, uint32_t& r2, uint32_t& r3, uint32_t addr) {
    asm volatile("ldmatrix.sync.aligned.m8n8.x4.shared.b16 {%0,%1,%2,%3}, [%4];"
                 : "=r"(r0), "=r"(r1), "=r"(r2), "=r"(r3) : "r"(addr));
}

// m16n8k16 fp16 inputs, fp16 accumulate: D/C are 2 packed-f16x2 regs.
static __device__ __forceinline__ void mma_f16acc(
    uint32_t* c, uint32_t a0, uint32_t a1, uint32_t a2, uint32_t a3,
    uint32_t b0, uint32_t b1) {
    asm volatile(
        "mma.sync.aligned.m16n8k16.row.col.f16.f16.f16.f16 "
        "{%0,%1}, {%2,%3,%4,%5}, {%6,%7}, {%0,%1};"
        : "+r"(c[0]), "+r"(c[1])
        : "r"(a0), "r"(a1), "r"(a2), "r"(a3), "r"(b0), "r"(b1));
}

static __device__ __forceinline__ uint32_t swz(uint32_t off) {
    return off ^ ((off >> 3) & 0x70);   // SW128: conflict-free 128B rows
}

// ---------------------------------------------------------------------------
// K1: per-row normalize fp32 -> fp16, and zero the output flags.
// ---------------------------------------------------------------------------
__global__ void __launch_bounds__(256) rqa_normalize(
    const float* __restrict__ Ex, const float* __restrict__ Ey,
    float* __restrict__ out)
{
    __shared__ float ws[8];
    const int row = blockIdx.x;
    const int tid = threadIdx.x;

    if (tid == 0) out[row] = 0.0f;

    // ---- X row ----
    {
        const float4* px = reinterpret_cast<const float4*>(Ex) + (size_t)row * 256;
        float4 v = px[tid];
        float ss = v.x * v.x + v.y * v.y + v.z * v.z + v.w * v.w;
        #pragma unroll
        for (int o = 16; o > 0; o >>= 1) ss += __shfl_xor_sync(0xFFFFFFFFu, ss, o);
        if ((tid & 31) == 0) ws[tid >> 5] = ss;
        __syncthreads();
        float tot = ws[0] + ws[1] + ws[2] + ws[3] + ws[4] + ws[5] + ws[6] + ws[7];
        float scale = 1.0f / fmaxf(sqrtf(tot), 1e-8f);
        __half2 h0 = __floats2half2_rn(v.x * scale, v.y * scale);
        __half2 h1 = __floats2half2_rn(v.z * scale, v.w * scale);
        uint2 u;
        u.x = *reinterpret_cast<uint32_t*>(&h0);
        u.y = *reinterpret_cast<uint32_t*>(&h1);
        reinterpret_cast<uint2*>(g_Xb4)[(size_t)row * 256 + tid] = u;
        __syncthreads();
    }
    // ---- Y row ----
    {
        const float4* py = reinterpret_cast<const float4*>(Ey) + (size_t)row * 256;
        float4 v = py[tid];
        float ss = v.x * v.x + v.y * v.y + v.z * v.z + v.w * v.w;
        #pragma unroll
        for (int o = 16; o > 0; o >>= 1) ss += __shfl_xor_sync(0xFFFFFFFFu, ss, o);
        if ((tid & 31) == 0) ws[tid >> 5] = ss;
        __syncthreads();
        float tot = ws[0] + ws[1] + ws[2] + ws[3] + ws[4] + ws[5] + ws[6] + ws[7];
        float scale = 1.0f / fmaxf(sqrtf(tot), 1e-8f);
        __half2 h0 = __floats2half2_rn(v.x * scale, v.y * scale);
        __half2 h1 = __floats2half2_rn(v.z * scale, v.w * scale);
        uint2 u;
        u.x = *reinterpret_cast<uint32_t*>(&h0);
        u.y = *reinterpret_cast<uint32_t*>(&h1);
        reinterpret_cast<uint2*>(g_Yb4)[(size_t)row * 256 + tid] = u;
    }
}

// ---------------------------------------------------------------------------
// K2: fp16 mma.sync GEMM (fp16 accumulate) + threshold + any-reduce.
// ---------------------------------------------------------------------------
__global__ void __launch_bounds__(GT_, 2) rqa_gemm(float* __restrict__ out)
{
    extern __shared__ char smem_raw[];
    const uint32_t sb = (smem_u32(smem_raw) + 1023u) & ~1023u;

    const int tid = threadIdx.x;
    const int wid = tid >> 5;
    const int lid = tid & 31;
    const int warp_m = wid & 3;       // 4 M-groups of 32 rows
    const int warp_n = wid >> 2;      // 2 N-groups of 64 cols
    const int tm = blockIdx.x;        // 64 M tiles
    const int tn = blockIdx.y;        // 64 N tiles

    const uint4* Ag = g_Xb4 + (size_t)tm * BM_ * (DIMS / 8);
    const uint4* Bg = g_Yb4 + (size_t)tn * BN_ * (DIMS / 8);

    // per-stage copy: A (128 rows x 8 uint4) then B (128 rows x 8 uint4)
    const int cp_row = tid >> 3;      // 0..31 base row, stepped by 32
    const int cp_v   = tid & 7;       // uint4 index within 128B row

    auto issue_stage = [&](int c, int s) {
        const uint32_t a_base = sb + s * STAGE_BYTES;
        const uint32_t b_base = a_base + BM_ * 128;
        #pragma unroll
        for (int i = 0; i < 4; i++) {
            const int row = cp_row + i * 32;
            const uint32_t off = swz((uint32_t)(row * 128 + cp_v * 16));
            cp_async16(a_base + off, Ag + (size_t)row * (DIMS / 8) + c * 8 + cp_v);
        }
        #pragma unroll
        for (int i = 0; i < 4; i++) {
            const int row = cp_row + i * 32;
            const uint32_t off = swz((uint32_t)(row * 128 + cp_v * 16));
            cp_async16(b_base + off, Bg + (size_t)row * (DIMS / 8) + c * 8 + cp_v);
        }
        CP_COMMIT();
    };

    // acc[i][j]: i = 2 M sub-tiles (16 rows apart), j = 8 n8 column groups.
    // Each entry: 2 packed f16x2 regs (rows +0 and +8 of the m16 tile).
    uint32_t acc[2][8][2];
    #pragma unroll
    for (int i = 0; i < 2; i++)
        #pragma unroll
        for (int j = 0; j < 8; j++) { acc[i][j][0] = 0u; acc[i][j][1] = 0u; }

    // prologue: prefetch 2 chunks
    issue_stage(0, 0);
    issue_stage(1, 1);

    // precomputed ldmatrix lane addressing
    const int a_row_l = warp_m * 32 + (lid & 15);
    const int a_kb_l  = (lid >> 4) * 16;
    const int b_mat  = lid >> 3;
    const int b_n_l  = warp_n * 64 + ((b_mat >> 1) & 1) * 8 + (lid & 7);
    const int b_kb_l = (b_mat & 1) * 16;

    #pragma unroll 1
    for (int c = 0; c < NCHUNK; c++) {
        CP_WAIT(1);
        __syncthreads();

        if (c + 2 < NCHUNK) issue_stage(c + 2, (c + 2) % STAGES);

        const int s = c % STAGES;
        const uint32_t a_base = sb + s * STAGE_BYTES;
        const uint32_t b_base = a_base + BM_ * 128;

        #pragma unroll
        for (int ks = 0; ks < 4; ks++) {
            uint32_t a[2][4];
            #pragma unroll
            for (int i = 0; i < 2; i++) {
                const uint32_t off =
                    swz((uint32_t)((a_row_l + i * 16) * 128 + ks * 32 + a_kb_l));
                ldmatrix_x4(a[i][0], a[i][1], a[i][2], a[i][3], a_base + off);
            }
            uint32_t b[4][4];
            #pragma unroll
            for (int j2 = 0; j2 < 4; j2++) {
                const uint32_t off =
                    swz((uint32_t)((b_n_l + j2 * 16) * 128 + ks * 32 + b_kb_l));
                ldmatrix_x4(b[j2][0], b[j2][1], b[j2][2], b[j2][3], b_base + off);
            }
            #pragma unroll
            for (int i = 0; i < 2; i++)
                #pragma unroll
                for (int j = 0; j < 8; j++) {
                    const int j2 = j >> 1, h = j & 1;
                    mma_f16acc(acc[i][j], a[i][0], a[i][1], a[i][2], a[i][3],
                               b[j2][2 * h], b[j2][2 * h + 1]);
                }
        }
    }

    // Epilogue: threshold + OR over this CTA's 128 N columns, then merge the
    // 4-lane quad so lane (lid&3)==0 holds the row verdict.
    // acc reg h: h=0 -> row base, h=1 -> row base + 8 (each packs 2 columns).
    const __half2 thr = __floats2half2_rn(0.9f, 0.9f);
    #pragma unroll
    for (int i = 0; i < 2; i++) {
        #pragma unroll
        for (int h = 0; h < 2; h++) {
            uint32_t f = 0;
            #pragma unroll
            for (int j = 0; j < 8; j++) {
                __half2 v = *reinterpret_cast<__half2*>(&acc[i][j][h]);
                __half2 g = __hgt2(v, thr);          // 1.0 per lane where v > 0.9
                f |= *reinterpret_cast<uint32_t*>(&g);
            }
            f |= __shfl_xor_sync(0xFFFFFFFFu, f, 1);
            f |= __shfl_xor_sync(0xFFFFFFFFu, f, 2);
            if ((lid & 3) == 0 && f) {
                const int row = tm * BM_ + warp_m * 32 + i * 16 + h * 8 + (lid >> 2);
                out[row] = 1.0f;   // benign same-value race across tn tiles
            }
        }
    }
}

// ---------------------------------------------------------------------------
// Launch
// ---------------------------------------------------------------------------
extern "C" void kernel_launch(void* const* d_in, const int* in_sizes, int n_in,
                              void* d_out, int out_size)
{
    const float* Ex = (const float*)d_in[0];
    const float* Ey = (const float*)d_in[1];
    float* out = (float*)d_out;

    cudaFuncSetAttribute(rqa_gemm, cudaFuncAttributeMaxDynamicSharedMemorySize, SMEM_DYN);

    rqa_normalize<<<NROWS, 256>>>(Ex, Ey, out);

    dim3 grid(NROWS / BM_, NROWS / BN_);
    rqa_gemm<<<grid, GT_, SMEM_DYN>>>(out);
}

// round 6
// speedup vs baseline: 2.0054x; 2.0054x over previous
#include <cuda_runtime.h>
#include <cstdint>

// ============================================================================
// simpleRQA: out[n] = any_m( cos_sim(Ex[n], Ey[m]) > 0.9 )
// Ex, Ey: [8192, 1024] fp32.  out: [8192] fp32 (0.0 / 1.0)
//
// K1: normalize rows (fp32 norm, clamp 1e-8), quantize to int8 (q=rint(127 v))
//     into scratch; zero out[].
// K2: int8 IMMA GEMM (m16n8k32, s32 accum; CTA tile 128x128, K-chunk 128B,
//     3-stage cp.async) fused with integer threshold (dot > 14516) + any-over-N.
//     Exact integer accumulation; threshold margin >> quantization noise.
// ============================================================================

#define NROWS   8192
#define DIMS    1024
#define BM_     128
#define BN_     128
#define NCHUNK  8                   // 8 chunks of 128 int8 (=128B rows)
#define STAGES  3
#define GT_     256                 // 8 warps: 4M x 2N
#define THR_I   14516               // floor(0.9 * 127 * 127)

#define STAGE_BYTES   (BM_ * 128 + BN_ * 128)   // 32 KB
#define SMEM_DYN      (STAGES * STAGE_BYTES + 1024)

// Quantized int8 operands (8 MB each), 16B-aligned.
static __device__ uint4 g_Xq[(size_t)NROWS * DIMS / 16];
static __device__ uint4 g_Yq[(size_t)NROWS * DIMS / 16];

// ---------------------------------------------------------------------------
// helpers
// ---------------------------------------------------------------------------
static __device__ __forceinline__ uint32_t smem_u32(const void* p) {
    uint32_t a;
    asm("{ .reg .u64 t; cvta.to.shared.u64 t, %1; cvt.u32.u64 %0, t; }"
        : "=r"(a) : "l"(p));
    return a;
}

static __device__ __forceinline__ void cp_async16(uint32_t dst, const void* src) {
    asm volatile("cp.async.cg.shared.global [%0], [%1], 16;"
                 :: "r"(dst), "l"(src) : "memory");
}
#define CP_COMMIT() asm volatile("cp.async.commit_group;" ::: "memory")
#define CP_WAIT(n)  asm volatile("cp.async.wait_group %0;" :: "n"(n) : "memory")

static __device__ __forceinline__ void ldmatrix_x4(
    uint32_t& r0, uint32_t& r1, uint32_t& r2, uint32_t& r3, uint32_t addr) {
    asm volatile("ldmatrix.sync.aligned.m8n8.x4.shared.b16 {%0,%1,%2,%3}, [%4];"
                 : "=r"(r0), "=r"(r1), "=r"(r2), "=r"(r3) : "r"(addr));
}

// m16n8k32 s8 x s8 -> s32 accumulate.
static __device__ __forceinline__ void mma_s8(
    int32_t* c, uint32_t a0, uint32_t a1, uint32_t a2, uint32_t a3,
    uint32_t b0, uint32_t b1) {
    asm volatile(
        "mma.sync.aligned.m16n8k32.row.col.s32.s8.s8.s32 "
        "{%0,%1,%2,%3}, {%4,%5,%6,%7}, {%8,%9}, {%0,%1,%2,%3};"
        : "+r"(c[0]), "+r"(c[1]), "+r"(c[2]), "+r"(c[3])
        : "r"(a0), "r"(a1), "r"(a2), "r"(a3), "r"(b0), "r"(b1));
}

static __device__ __forceinline__ uint32_t swz(uint32_t off) {
    return off ^ ((off >> 3) & 0x70);   // SW128: conflict-free 128B rows
}

// ---------------------------------------------------------------------------
// K1: per-row normalize fp32 -> int8 (q = rint(127 * v / ||v||)); zero out[].
// ---------------------------------------------------------------------------
__global__ void __launch_bounds__(256) rqa_normalize(
    const float* __restrict__ Ex, const float* __restrict__ Ey,
    float* __restrict__ out)
{
    __shared__ float ws[8];
    const int row = blockIdx.x;
    const int tid = threadIdx.x;

    if (tid == 0) out[row] = 0.0f;

    // ---- X row ----
    {
        const float4* px = reinterpret_cast<const float4*>(Ex) + (size_t)row * 256;
        float4 v = px[tid];
        float ss = v.x * v.x + v.y * v.y + v.z * v.z + v.w * v.w;
        #pragma unroll
        for (int o = 16; o > 0; o >>= 1) ss += __shfl_xor_sync(0xFFFFFFFFu, ss, o);
        if ((tid & 31) == 0) ws[tid >> 5] = ss;
        __syncthreads();
        float tot = ws[0] + ws[1] + ws[2] + ws[3] + ws[4] + ws[5] + ws[6] + ws[7];
        float sc = 127.0f / fmaxf(sqrtf(tot), 1e-8f);
        int q0 = max(-127, min(127, __float2int_rn(v.x * sc)));
        int q1 = max(-127, min(127, __float2int_rn(v.y * sc)));
        int q2 = max(-127, min(127, __float2int_rn(v.z * sc)));
        int q3 = max(-127, min(127, __float2int_rn(v.w * sc)));
        uint32_t p = (uint32_t)(q0 & 0xFF) | ((uint32_t)(q1 & 0xFF) << 8) |
                     ((uint32_t)(q2 & 0xFF) << 16) | ((uint32_t)(q3 & 0xFF) << 24);
        reinterpret_cast<uint32_t*>(g_Xq)[(size_t)row * 256 + tid] = p;
        __syncthreads();
    }
    // ---- Y row ----
    {
        const float4* py = reinterpret_cast<const float4*>(Ey) + (size_t)row * 256;
        float4 v = py[tid];
        float ss = v.x * v.x + v.y * v.y + v.z * v.z + v.w * v.w;
        #pragma unroll
        for (int o = 16; o > 0; o >>= 1) ss += __shfl_xor_sync(0xFFFFFFFFu, ss, o);
        if ((tid & 31) == 0) ws[tid >> 5] = ss;
        __syncthreads();
        float tot = ws[0] + ws[1] + ws[2] + ws[3] + ws[4] + ws[5] + ws[6] + ws[7];
        float sc = 127.0f / fmaxf(sqrtf(tot), 1e-8f);
        int q0 = max(-127, min(127, __float2int_rn(v.x * sc)));
        int q1 = max(-127, min(127, __float2int_rn(v.y * sc)));
        int q2 = max(-127, min(127, __float2int_rn(v.z * sc)));
        int q3 = max(-127, min(127, __float2int_rn(v.w * sc)));
        uint32_t p = (uint32_t)(q0 & 0xFF) | ((uint32_t)(q1 & 0xFF) << 8) |
                     ((uint32_t)(q2 & 0xFF) << 16) | ((uint32_t)(q3 & 0xFF) << 24);
        reinterpret_cast<uint32_t*>(g_Yq)[(size_t)row * 256 + tid] = p;
    }
}

// ---------------------------------------------------------------------------
// K2: int8 IMMA GEMM + integer threshold + any-reduce.
// Each 128B SMEM row = one full K-chunk of 128 int8.
// ---------------------------------------------------------------------------
__global__ void __launch_bounds__(GT_, 2) rqa_gemm(float* __restrict__ out)
{
    extern __shared__ char smem_raw[];
    const uint32_t sb = (smem_u32(smem_raw) + 1023u) & ~1023u;

    const int tid = threadIdx.x;
    const int wid = tid >> 5;
    const int lid = tid & 31;
    const int warp_m = wid & 3;       // 4 M-groups of 32 rows
    const int warp_n = wid >> 2;      // 2 N-groups of 64 cols
    const int tm = blockIdx.x;        // 64 M tiles
    const int tn = blockIdx.y;        // 64 N tiles

    // row stride = 1024 B = 64 uint4; chunk c = uint4 [c*8, c*8+8)
    const uint4* Ag = g_Xq + (size_t)tm * BM_ * 64;
    const uint4* Bg = g_Yq + (size_t)tn * BN_ * 64;

    const int cp_row = tid >> 3;      // 0..31 base row, stepped by 32
    const int cp_v   = tid & 7;       // uint4 index within 128B row

    auto issue_stage = [&](int c, int s) {
        const uint32_t a_base = sb + s * STAGE_BYTES;
        const uint32_t b_base = a_base + BM_ * 128;
        #pragma unroll
        for (int i = 0; i < 4; i++) {
            const int row = cp_row + i * 32;
            const uint32_t off = swz((uint32_t)(row * 128 + cp_v * 16));
            cp_async16(a_base + off, Ag + (size_t)row * 64 + c * 8 + cp_v);
        }
        #pragma unroll
        for (int i = 0; i < 4; i++) {
            const int row = cp_row + i * 32;
            const uint32_t off = swz((uint32_t)(row * 128 + cp_v * 16));
            cp_async16(b_base + off, Bg + (size_t)row * 64 + c * 8 + cp_v);
        }
        CP_COMMIT();
    };

    // acc[i][j]: i = 2 M sub-tiles (16 rows apart), j = 8 n8 column groups.
    int32_t acc[2][8][4];
    #pragma unroll
    for (int i = 0; i < 2; i++)
        #pragma unroll
        for (int j = 0; j < 8; j++)
            #pragma unroll
            for (int k = 0; k < 4; k++) acc[i][j][k] = 0;

    issue_stage(0, 0);
    issue_stage(1, 1);

    // ldmatrix lane addressing (per k32 step, 32B of each row)
    // A: lanes 0-15 -> rows 0-15 at +0B; lanes 16-31 -> rows 0-15 at +16B.
    const int a_row_l = warp_m * 32 + (lid & 15);
    const int a_kb_l  = (lid >> 4) * 16;
    // B: lanes 0-7: n0-7 +0B; 8-15: n0-7 +16B; 16-23: n8-15 +0B; 24-31: n8-15 +16B.
    const int b_n_l  = warp_n * 64 + ((lid >> 4) & 1) * 8 + (lid & 7);
    const int b_kb_l = ((lid >> 3) & 1) * 16;

    #pragma unroll 1
    for (int c = 0; c < NCHUNK; c++) {
        CP_WAIT(1);
        __syncthreads();

        if (c + 2 < NCHUNK) issue_stage(c + 2, (c + 2) % STAGES);

        const int s = c % STAGES;
        const uint32_t a_base = sb + s * STAGE_BYTES;
        const uint32_t b_base = a_base + BM_ * 128;

        #pragma unroll
        for (int ks = 0; ks < 4; ks++) {       // 4 x k32 = 128 int8
            uint32_t a[2][4];
            #pragma unroll
            for (int i = 0; i < 2; i++) {
                const uint32_t off =
                    swz((uint32_t)((a_row_l + i * 16) * 128 + ks * 32 + a_kb_l));
                ldmatrix_x4(a[i][0], a[i][1], a[i][2], a[i][3], a_base + off);
            }
            // b[j2]: r0=b0 (lower n8), r1=b1 (lower), r2=b0 (upper n8), r3=b1 (upper)
            uint32_t b[4][4];
            #pragma unroll
            for (int j2 = 0; j2 < 4; j2++) {
                const uint32_t off =
                    swz((uint32_t)((b_n_l + j2 * 16) * 128 + ks * 32 + b_kb_l));
                ldmatrix_x4(b[j2][0], b[j2][1], b[j2][2], b[j2][3], b_base + off);
            }
            #pragma unroll
            for (int i = 0; i < 2; i++)
                #pragma unroll
                for (int j = 0; j < 8; j++) {
                    const int j2 = j >> 1, h = j & 1;
                    mma_s8(acc[i][j], a[i][0], a[i][1], a[i][2], a[i][3],
                           b[j2][2 * h], b[j2][2 * h + 1]);
                }
        }
    }

    // Epilogue: integer threshold + OR over this CTA's 128 N columns, quad-merge.
    // c0,c1 = row base (cols 2q, 2q+1); c2,c3 = row base + 8.
    #pragma unroll
    for (int i = 0; i < 2; i++) {
        #pragma unroll
        for (int h = 0; h < 2; h++) {
            int f = 0;
            #pragma unroll
            for (int j = 0; j < 8; j++)
                f |= (acc[i][j][2 * h] > THR_I) | (acc[i][j][2 * h + 1] > THR_I);
            f |= __shfl_xor_sync(0xFFFFFFFFu, f, 1);
            f |= __shfl_xor_sync(0xFFFFFFFFu, f, 2);
            if ((lid & 3) == 0 && f) {
                const int row = tm * BM_ + warp_m * 32 + i * 16 + h * 8 + (lid >> 2);
                out[row] = 1.0f;   // benign same-value race across tn tiles
            }
        }
    }
}

// ---------------------------------------------------------------------------
// Launch
// ---------------------------------------------------------------------------
extern "C" void kernel_launch(void* const* d_in, const int* in_sizes, int n_in,
                              void* d_out, int out_size)
{
    const float* Ex = (const float*)d_in[0];
    const float* Ey = (const float*)d_in[1];
    float* out = (float*)d_out;

    cudaFuncSetAttribute(rqa_gemm, cudaFuncAttributeMaxDynamicSharedMemorySize, SMEM_DYN);

    rqa_normalize<<<NROWS, 256>>>(Ex, Ey, out);

    dim3 grid(NROWS / BM_, NROWS / BN_);
    rqa_gemm<<<grid, GT_, SMEM_DYN>>>(out);
}

// round 8
// speedup vs baseline: 2.7078x; 1.3503x over previous
#include <cuda_runtime.h>
#include <cstdint>

// ============================================================================
// simpleRQA: out[n] = any_m( cos_sim(Ex[n], Ey[m]) > 0.9 )
// Ex, Ey: [8192, 1024] fp32.  out: [8192] fp32 (0.0 / 1.0)
//
// K0: zero flags/out/maxima.
// K1: normalize+quantize rows to int8; per-row head/tail/residual norms ->
//     atomicMax global bounds.
// K2: int8 IMMA GEMM over HEAD 512 dims only; conservative (worst-case exact,
//     Cauchy-Schwarz) screen flags rows that could possibly exceed sim 0.9.
// K3: exact fp32 fallback for flagged rows (statistically none).
// ============================================================================

#define NROWS   8192
#define DIMS    1024
#define HEAD    512
#define BM_     128
#define BN_     128
#define NCHUNK  4                   // 4 chunks of 128 int8 = 512 head dims
#define STAGES  3
#define GT_     256                 // 8 warps: 4M x 2N

#define STAGE_BYTES   (BM_ * 128 + BN_ * 128)   // 32 KB
#define SMEM_DYN      (STAGES * STAGE_BYTES + 1024)

// Quantized int8 operands (8 MB each; full 1024-dim layout, row stride 1KB).
static __device__ uint4 g_Xq[(size_t)NROWS * DIMS / 16];
static __device__ uint4 g_Yq[(size_t)NROWS * DIMS / 16];
static __device__ int   g_flag[NROWS];
// maxima as positive-float bits for int atomicMax:
// [0]=Ex(resid) [1]=Hx(head) [2]=Tx(tail) [3]=Ey [4]=Hy [5]=Ty
static __device__ int   g_max6[6];

// ---------------------------------------------------------------------------
// helpers
// ---------------------------------------------------------------------------
static __device__ __forceinline__ uint32_t smem_u32(const void* p) {
    uint32_t a;
    asm("{ .reg .u64 t; cvta.to.shared.u64 t, %1; cvt.u32.u64 %0, t; }"
        : "=r"(a) : "l"(p));
    return a;
}

static __device__ __forceinline__ void cp_async16(uint32_t dst, const void* src) {
    asm volatile("cp.async.cg.shared.global [%0], [%1], 16;"
                 :: "r"(dst), "l"(src) : "memory");
}
#define CP_COMMIT() asm volatile("cp.async.commit_group;" ::: "memory")
#define CP_WAIT(n)  asm volatile("cp.async.wait_group %0;" :: "n"(n) : "memory")

static __device__ __forceinline__ void ldmatrix_x4(
    uint32_t& r0, uint32_t& r1, uint32_t& r2, uint32_t& r3, uint32_t addr) {
    asm volatile("ldmatrix.sync.aligned.m8n8.x4.shared.b16 {%0,%1,%2,%3}, [%4];"
                 : "=r"(r0), "=r"(r1), "=r"(r2), "=r"(r3) : "r"(addr));
}

static __device__ __forceinline__ void mma_s8(
    int32_t* c, uint32_t a0, uint32_t a1, uint32_t a2, uint32_t a3,
    uint32_t b0, uint32_t b1) {
    asm volatile(
        "mma.sync.aligned.m16n8k32.row.col.s32.s8.s8.s32 "
        "{%0,%1,%2,%3}, {%4,%5,%6,%7}, {%8,%9}, {%0,%1,%2,%3};"
        : "+r"(c[0]), "+r"(c[1]), "+r"(c[2]), "+r"(c[3])
        : "r"(a0), "r"(a1), "r"(a2), "r"(a3), "r"(b0), "r"(b1));
}

static __device__ __forceinline__ uint32_t swz(uint32_t off) {
    return off ^ ((off >> 3) & 0x70);
}

static __device__ __forceinline__ float blk_sum(float v, float* ws, int tid) {
    #pragma unroll
    for (int o = 16; o > 0; o >>= 1) v += __shfl_xor_sync(0xFFFFFFFFu, v, o);
    if ((tid & 31) == 0) ws[tid >> 5] = v;
    __syncthreads();
    float t = ws[0] + ws[1] + ws[2] + ws[3] + ws[4] + ws[5] + ws[6] + ws[7];
    __syncthreads();
    return t;
}

// ---------------------------------------------------------------------------
// K0: reset flags, maxima, out.
// ---------------------------------------------------------------------------
__global__ void __launch_bounds__(256) rqa_init(float* __restrict__ out)
{
    const int i = blockIdx.x * 256 + threadIdx.x;
    g_flag[i] = 0;
    out[i] = 0.0f;
    if (i < 6) g_max6[i] = 0;
}

// ---------------------------------------------------------------------------
// K1: normalize -> int8 quantize; per-row E (resid), H (head), T (tail) norms.
// One block per row; handles Ex[row] and Ey[row].
// ---------------------------------------------------------------------------
__global__ void __launch_bounds__(256) rqa_normalize(
    const float* __restrict__ Ex, const float* __restrict__ Ey)
{
    __shared__ float ws[8];
    const int row = blockIdx.x;
    const int tid = threadIdx.x;
    const bool head = (tid < 128);          // threads 0-127 hold dims 0-511

    #pragma unroll 1
    for (int side = 0; side < 2; side++) {
        const float4* src = reinterpret_cast<const float4*>(side ? Ey : Ex)
                            + (size_t)row * 256;
        uint32_t* dst = reinterpret_cast<uint32_t*>(side ? g_Yq : g_Xq)
                        + (size_t)row * 256;
        const int mb = side ? 3 : 0;

        float4 v = src[tid];
        float ss = blk_sum(v.x * v.x + v.y * v.y + v.z * v.z + v.w * v.w, ws, tid);
        float norm = fmaxf(sqrtf(ss), 1e-8f);
        float sc = 127.0f / norm;

        float f0 = v.x * sc, f1 = v.y * sc, f2 = v.z * sc, f3 = v.w * sc;
        int q0 = max(-127, min(127, __float2int_rn(f0)));
        int q1 = max(-127, min(127, __float2int_rn(f1)));
        int q2 = max(-127, min(127, __float2int_rn(f2)));
        int q3 = max(-127, min(127, __float2int_rn(f3)));
        uint32_t p = (uint32_t)(q0 & 0xFF) | ((uint32_t)(q1 & 0xFF) << 8) |
                     ((uint32_t)(q2 & 0xFF) << 16) | ((uint32_t)(q3 & 0xFF) << 24);
        dst[tid] = p;

        // head-only stats: residual^2 (q units) and raw head sum-sq
        float e0 = (float)q0 - f0, e1 = (float)q1 - f1,
              e2 = (float)q2 - f2, e3 = (float)q3 - f3;
        float e2s = head ? (e0 * e0 + e1 * e1 + e2 * e2 + e3 * e3) : 0.0f;
        float hss = head ? (v.x * v.x + v.y * v.y + v.z * v.z + v.w * v.w) : 0.0f;
        float e2t = blk_sum(e2s, ws, tid);
        float hst = blk_sum(hss, ws, tid);

        if (tid == 0) {
            float E = sqrtf(e2t);                       // ||resid_head|| (q units)
            float H = sqrtf(hst) / norm;                // ||x_hat_head||
            float T = sqrtf(fmaxf(ss - hst, 0.0f)) / norm;  // ||x_hat_tail||
            atomicMax(&g_max6[mb + 0], __float_as_int(E));
            atomicMax(&g_max6[mb + 1], __float_as_int(H));
            atomicMax(&g_max6[mb + 2], __float_as_int(T));
        }
        __syncthreads();
    }
}

// ---------------------------------------------------------------------------
// K2: int8 IMMA GEMM over head 512 dims + conservative screen -> g_flag.
// ---------------------------------------------------------------------------
__global__ void __launch_bounds__(GT_, 2) rqa_gemm()
{
    extern __shared__ char smem_raw[];
    const uint32_t sb = (smem_u32(smem_raw) + 1023u) & ~1023u;

    const int tid = threadIdx.x;
    const int wid = tid >> 5;
    const int lid = tid & 31;
    const int warp_m = wid & 3;
    const int warp_n = wid >> 2;
    const int tm = blockIdx.x;
    const int tn = blockIdx.y;

    // Conservative integer screen threshold (worst-case exact):
    //   dot_full <= Q/127^2 + slack + Tx*Ty, so flag iff Q > thr where
    //   thr = floor((0.9 - Tx*Ty - slack) * 127^2) - 1.
    const float Exm = __int_as_float(g_max6[0]);
    const float Hxm = __int_as_float(g_max6[1]);
    const float Txm = __int_as_float(g_max6[2]);
    const float Eym = __int_as_float(g_max6[3]);
    const float Hym = __int_as_float(g_max6[4]);
    const float Tym = __int_as_float(g_max6[5]);
    const float slack = (Exm * Hym + Eym * Hxm) * (1.0f / 127.0f)
                      + (Exm * Eym) * (1.0f / 16129.0f);
    const float cut = 0.9f - Txm * Tym - slack;
    const int thr = (int)floorf(cut * 16129.0f) - 1;

    const uint4* Ag = g_Xq + (size_t)tm * BM_ * 64;   // row stride 64 uint4 (1KB)
    const uint4* Bg = g_Yq + (size_t)tn * BN_ * 64;

    const int cp_row = tid >> 3;
    const int cp_v   = tid & 7;

    auto issue_stage = [&](int c, int s) {
        const uint32_t a_base = sb + s * STAGE_BYTES;
        const uint32_t b_base = a_base + BM_ * 128;
        #pragma unroll
        for (int i = 0; i < 4; i++) {
            const int row = cp_row + i * 32;
            const uint32_t off = swz((uint32_t)(row * 128 + cp_v * 16));
            cp_async16(a_base + off, Ag + (size_t)row * 64 + c * 8 + cp_v);
        }
        #pragma unroll
        for (int i = 0; i < 4; i++) {
            const int row = cp_row + i * 32;
            const uint32_t off = swz((uint32_t)(row * 128 + cp_v * 16));
            cp_async16(b_base + off, Bg + (size_t)row * 64 + c * 8 + cp_v);
        }
        CP_COMMIT();
    };

    int32_t acc[2][8][4];
    #pragma unroll
    for (int i = 0; i < 2; i++)
        #pragma unroll
        for (int j = 0; j < 8; j++)
            #pragma unroll
            for (int k = 0; k < 4; k++) acc[i][j][k] = 0;

    issue_stage(0, 0);
    issue_stage(1, 1);

    const int a_row_l = warp_m * 32 + (lid & 15);
    const int a_kb_l  = (lid >> 4) * 16;
    const int b_n_l  = warp_n * 64 + ((lid >> 4) & 1) * 8 + (lid & 7);
    const int b_kb_l = ((lid >> 3) & 1) * 16;

    #pragma unroll 1
    for (int c = 0; c < NCHUNK; c++) {
        CP_WAIT(1);
        __syncthreads();

        if (c + 2 < NCHUNK) issue_stage(c + 2, (c + 2) % STAGES);

        const int s = c % STAGES;
        const uint32_t a_base = sb + s * STAGE_BYTES;
        const uint32_t b_base = a_base + BM_ * 128;

        #pragma unroll
        for (int ks = 0; ks < 4; ks++) {
            uint32_t a[2][4];
            #pragma unroll
            for (int i = 0; i < 2; i++) {
                const uint32_t off =
                    swz((uint32_t)((a_row_l + i * 16) * 128 + ks * 32 + a_kb_l));
                ldmatrix_x4(a[i][0], a[i][1], a[i][2], a[i][3], a_base + off);
            }
            uint32_t b[4][4];
            #pragma unroll
            for (int j2 = 0; j2 < 4; j2++) {
                const uint32_t off =
                    swz((uint32_t)((b_n_l + j2 * 16) * 128 + ks * 32 + b_kb_l));
                ldmatrix_x4(b[j2][0], b[j2][1], b[j2][2], b[j2][3], b_base + off);
            }
            #pragma unroll
            for (int i = 0; i < 2; i++)
                #pragma unroll
                for (int j = 0; j < 8; j++) {
                    const int j2 = j >> 1, h = j & 1;
                    mma_s8(acc[i][j], a[i][0], a[i][1], a[i][2], a[i][3],
                           b[j2][2 * h], b[j2][2 * h + 1]);
                }
        }
    }

    // Screen: flag rows whose head Q-dot could exceed the bound.
    #pragma unroll
    for (int i = 0; i < 2; i++) {
        #pragma unroll
        for (int h = 0; h < 2; h++) {
            int f = 0;
            #pragma unroll
            for (int j = 0; j < 8; j++)
                f |= (acc[i][j][2 * h] > thr) | (acc[i][j][2 * h + 1] > thr);
            f |= __shfl_xor_sync(0xFFFFFFFFu, f, 1);
            f |= __shfl_xor_sync(0xFFFFFFFFu, f, 2);
            if ((lid & 3) == 0 && f) {
                const int row = tm * BM_ + warp_m * 32 + i * 16 + h * 8 + (lid >> 2);
                g_flag[row] = 1;   // benign race
            }
        }
    }
}

// ---------------------------------------------------------------------------
// K3: exact fp32 fallback for flagged rows (normally zero rows).
// ---------------------------------------------------------------------------
__global__ void __launch_bounds__(256) rqa_fallback(
    const float* __restrict__ Ex, const float* __restrict__ Ey,
    float* __restrict__ out)
{
    const int row = blockIdx.x;
    if (g_flag[row] == 0) return;

    __shared__ float xs[DIMS];
    __shared__ float ws[8];
    const int tid = threadIdx.x;

    float4 v = reinterpret_cast<const float4*>(Ex)[(size_t)row * 256 + tid];
    float ss = blk_sum(v.x * v.x + v.y * v.y + v.z * v.z + v.w * v.w, ws, tid);
    xs[tid * 4 + 0] = v.x; xs[tid * 4 + 1] = v.y;
    xs[tid * 4 + 2] = v.z; xs[tid * 4 + 3] = v.w;
    __syncthreads();
    const float nx = fmaxf(sqrtf(ss), 1e-8f);

    int any = 0;
    for (int m = tid; m < NROWS; m += 256) {
        const float* y = Ey + (size_t)m * DIMS;
        float dot = 0.0f, ssy = 0.0f;
        #pragma unroll 4
        for (int k = 0; k < DIMS; k++) {
            float yv = y[k];
            dot += xs[k] * yv;
            ssy += yv * yv;
        }
        float ny = fmaxf(sqrtf(ssy), 1e-8f);
        if (dot > 0.9f * nx * ny) any = 1;
    }
    if (any) out[row] = 1.0f;
}

// ---------------------------------------------------------------------------
// Launch
// ---------------------------------------------------------------------------
extern "C" void kernel_launch(void* const* d_in, const int* in_sizes, int n_in,
                              void* d_out, int out_size)
{
    const float* Ex = (const float*)d_in[0];
    const float* Ey = (const float*)d_in[1];
    float* out = (float*)d_out;

    cudaFuncSetAttribute(rqa_gemm, cudaFuncAttributeMaxDynamicSharedMemorySize, SMEM_DYN);

    rqa_init<<<NROWS / 256, 256>>>(out);
    rqa_normalize<<<NROWS, 256>>>(Ex, Ey);
    dim3 grid(NROWS / BM_, NROWS / BN_);
    rqa_gemm<<<grid, GT_, SMEM_DYN>>>();
    rqa_fallback<<<NROWS, 256>>>(Ex, Ey, out);
}

// round 9
// speedup vs baseline: 2.8112x; 1.0382x over previous
#include <cuda_runtime.h>
#include <cstdint>

// ============================================================================
// simpleRQA: out[n] = any_m( cos_sim(Ex[n], Ey[m]) > 0.9 )
// Ex, Ey: [8192, 1024] fp32.  out: [8192] fp32 (0.0 / 1.0)
//
// K0: zero the 6 atomicMax cells.
// K1: normalize+quantize rows to int8; per-row head/tail/residual norms ->
//     atomicMax global bounds; zero out[] and flags.
// K2: int8 IMMA GEMM over HEAD 512 dims; A-tile (64KB) resident in SMEM,
//     each CTA loops 4 tn tiles streaming only B chunks (3-stage cp.async).
//     Conservative (worst-case exact, Cauchy-Schwarz) screen -> g_flag.
// K3: exact fp32 fallback for flagged rows (statistically none).
// ============================================================================

#define NROWS   8192
#define DIMS    1024
#define BM_     128
#define BN_     128
#define NCHUNK  4                   // 4 chunks of 128 int8 = 512 head dims
#define NSPLIT  4                   // tn tiles per CTA
#define NQ      (NCHUNK * NSPLIT)   // 16 streamed B chunks per CTA
#define GT_     256                 // 8 warps: 4M x 2N

#define A_BYTES      (NCHUNK * BM_ * 128)     // 64 KB resident A
#define B_STAGE      (BN_ * 128)              // 16 KB per B stage
#define SMEM_DYN     (A_BYTES + 3 * B_STAGE + 1024)

// Quantized int8 operands (8 MB each; full 1024-dim layout, row stride 1KB).
static __device__ uint4 g_Xq[(size_t)NROWS * DIMS / 16];
static __device__ uint4 g_Yq[(size_t)NROWS * DIMS / 16];
static __device__ int   g_flag[NROWS];
// maxima as positive-float bits for int atomicMax:
// [0]=Ex(resid) [1]=Hx(head) [2]=Tx(tail) [3]=Ey [4]=Hy [5]=Ty
static __device__ int   g_max6[6];

// ---------------------------------------------------------------------------
// helpers
// ---------------------------------------------------------------------------
static __device__ __forceinline__ uint32_t smem_u32(const void* p) {
    uint32_t a;
    asm("{ .reg .u64 t; cvta.to.shared.u64 t, %1; cvt.u32.u64 %0, t; }"
        : "=r"(a) : "l"(p));
    return a;
}

static __device__ __forceinline__ void cp_async16(uint32_t dst, const void* src) {
    asm volatile("cp.async.cg.shared.global [%0], [%1], 16;"
                 :: "r"(dst), "l"(src) : "memory");
}
#define CP_COMMIT() asm volatile("cp.async.commit_group;" ::: "memory")
#define CP_WAIT(n)  asm volatile("cp.async.wait_group %0;" :: "n"(n) : "memory")

static __device__ __forceinline__ void ldmatrix_x4(
    uint32_t& r0, uint32_t& r1, uint32_t& r2, uint32_t& r3, uint32_t addr) {
    asm volatile("ldmatrix.sync.aligned.m8n8.x4.shared.b16 {%0,%1,%2,%3}, [%4];"
                 : "=r"(r0), "=r"(r1), "=r"(r2), "=r"(r3) : "r"(addr));
}

static __device__ __forceinline__ void mma_s8(
    int32_t* c, uint32_t a0, uint32_t a1, uint32_t a2, uint32_t a3,
    uint32_t b0, uint32_t b1) {
    asm volatile(
        "mma.sync.aligned.m16n8k32.row.col.s32.s8.s8.s32 "
        "{%0,%1,%2,%3}, {%4,%5,%6,%7}, {%8,%9}, {%0,%1,%2,%3};"
        : "+r"(c[0]), "+r"(c[1]), "+r"(c[2]), "+r"(c[3])
        : "r"(a0), "r"(a1), "r"(a2), "r"(a3), "r"(b0), "r"(b1));
}

static __device__ __forceinline__ uint32_t swz(uint32_t off) {
    return off ^ ((off >> 3) & 0x70);
}

static __device__ __forceinline__ float blk_sum(float v, float* ws, int tid) {
    #pragma unroll
    for (int o = 16; o > 0; o >>= 1) v += __shfl_xor_sync(0xFFFFFFFFu, v, o);
    if ((tid & 31) == 0) ws[tid >> 5] = v;
    __syncthreads();
    float t = ws[0] + ws[1] + ws[2] + ws[3] + ws[4] + ws[5] + ws[6] + ws[7];
    __syncthreads();
    return t;
}

// ---------------------------------------------------------------------------
// K0: reset maxima.
// ---------------------------------------------------------------------------
__global__ void rqa_init()
{
    if (threadIdx.x < 6) g_max6[threadIdx.x] = 0;
}

// ---------------------------------------------------------------------------
// K1: normalize -> int8 quantize; per-row E (resid), H (head), T (tail) norms.
// One block per row; handles Ex[row] and Ey[row]. Also zeroes out[]/flags.
// ---------------------------------------------------------------------------
__global__ void __launch_bounds__(256) rqa_normalize(
    const float* __restrict__ Ex, const float* __restrict__ Ey,
    float* __restrict__ out)
{
    __shared__ float ws[8];
    const int row = blockIdx.x;
    const int tid = threadIdx.x;
    const bool head = (tid < 128);          // threads 0-127 hold dims 0-511

    if (tid == 0) { out[row] = 0.0f; g_flag[row] = 0; }

    #pragma unroll 1
    for (int side = 0; side < 2; side++) {
        const float4* src = reinterpret_cast<const float4*>(side ? Ey : Ex)
                            + (size_t)row * 256;
        uint32_t* dst = reinterpret_cast<uint32_t*>(side ? g_Yq : g_Xq)
                        + (size_t)row * 256;
        const int mb = side ? 3 : 0;

        float4 v = src[tid];
        float ss = blk_sum(v.x * v.x + v.y * v.y + v.z * v.z + v.w * v.w, ws, tid);
        float norm = fmaxf(sqrtf(ss), 1e-8f);
        float sc = 127.0f / norm;

        float f0 = v.x * sc, f1 = v.y * sc, f2 = v.z * sc, f3 = v.w * sc;
        int q0 = max(-127, min(127, __float2int_rn(f0)));
        int q1 = max(-127, min(127, __float2int_rn(f1)));
        int q2 = max(-127, min(127, __float2int_rn(f2)));
        int q3 = max(-127, min(127, __float2int_rn(f3)));
        uint32_t p = (uint32_t)(q0 & 0xFF) | ((uint32_t)(q1 & 0xFF) << 8) |
                     ((uint32_t)(q2 & 0xFF) << 16) | ((uint32_t)(q3 & 0xFF) << 24);
        dst[tid] = p;

        float e0 = (float)q0 - f0, e1 = (float)q1 - f1,
              e2 = (float)q2 - f2, e3 = (float)q3 - f3;
        float e2s = head ? (e0 * e0 + e1 * e1 + e2 * e2 + e3 * e3) : 0.0f;
        float hss = head ? (v.x * v.x + v.y * v.y + v.z * v.z + v.w * v.w) : 0.0f;
        float e2t = blk_sum(e2s, ws, tid);
        float hst = blk_sum(hss, ws, tid);

        if (tid == 0) {
            float E = sqrtf(e2t);                           // ||resid_head|| (q units)
            float H = sqrtf(hst) / norm;                    // ||x_hat_head||
            float T = sqrtf(fmaxf(ss - hst, 0.0f)) / norm;  // ||x_hat_tail||
            atomicMax(&g_max6[mb + 0], __float_as_int(E));
            atomicMax(&g_max6[mb + 1], __float_as_int(H));
            atomicMax(&g_max6[mb + 2], __float_as_int(T));
        }
        __syncthreads();
    }
}

// ---------------------------------------------------------------------------
// K2: resident-A int8 IMMA GEMM over head 512 dims + conservative screen.
// grid = (64 tm, 16 tn-groups); each CTA does NSPLIT=4 consecutive tn tiles.
// SMEM: A[4 chunks x 16KB] | B stages[3 x 16KB].
// ---------------------------------------------------------------------------
__global__ void __launch_bounds__(GT_, 2) rqa_gemm()
{
    extern __shared__ char smem_raw[];
    const uint32_t sb = (smem_u32(smem_raw) + 1023u) & ~1023u;
    const uint32_t a_region = sb;
    const uint32_t b_region = sb + A_BYTES;

    const int tid = threadIdx.x;
    const int wid = tid >> 5;
    const int lid = tid & 31;
    const int warp_m = wid & 3;
    const int warp_n = wid >> 2;
    const int tm = blockIdx.x;                 // 64 M tiles
    const int tn0 = blockIdx.y * NSPLIT;       // first of 4 tn tiles

    // Conservative integer screen threshold (worst-case exact):
    const float Exm = __int_as_float(g_max6[0]);
    const float Hxm = __int_as_float(g_max6[1]);
    const float Txm = __int_as_float(g_max6[2]);
    const float Eym = __int_as_float(g_max6[3]);
    const float Hym = __int_as_float(g_max6[4]);
    const float Tym = __int_as_float(g_max6[5]);
    const float slack = (Exm * Hym + Eym * Hxm) * (1.0f / 127.0f)
                      + (Exm * Eym) * (1.0f / 16129.0f);
    const float cut = 0.9f - Txm * Tym - slack;
    const int thr = (int)floorf(cut * 16129.0f) - 1;

    const uint4* Ag = g_Xq + (size_t)tm * BM_ * 64;    // row stride 64 uint4 (1KB)

    const int cp_row = tid >> 3;               // 0..31 base row, stepped by 32
    const int cp_v   = tid & 7;                // uint4 index within 128B row

    // ---- prologue: load full A (4 chunks) as one group, then B0, B1 ----
    #pragma unroll
    for (int c = 0; c < NCHUNK; c++) {
        const uint32_t a_base = a_region + c * B_STAGE;
        #pragma unroll
        for (int i = 0; i < 4; i++) {
            const int row = cp_row + i * 32;
            const uint32_t off = swz((uint32_t)(row * 128 + cp_v * 16));
            cp_async16(a_base + off, Ag + (size_t)row * 64 + c * 8 + cp_v);
        }
    }
    CP_COMMIT();

    auto issue_B = [&](int q) {                // q in [0, NQ)
        const int tn = tn0 + (q >> 2);
        const int c  = q & 3;
        const uint4* Bg = g_Yq + (size_t)tn * BN_ * 64;
        const uint32_t b_base = b_region + (q % 3) * B_STAGE;
        #pragma unroll
        for (int i = 0; i < 4; i++) {
            const int row = cp_row + i * 32;
            const uint32_t off = swz((uint32_t)(row * 128 + cp_v * 16));
            cp_async16(b_base + off, Bg + (size_t)row * 64 + c * 8 + cp_v);
        }
        CP_COMMIT();
    };

    issue_B(0);
    issue_B(1);

    const int a_row_l = warp_m * 32 + (lid & 15);
    const int a_kb_l  = (lid >> 4) * 16;
    const int b_n_l  = warp_n * 64 + ((lid >> 4) & 1) * 8 + (lid & 7);
    const int b_kb_l = ((lid >> 3) & 1) * 16;

    int32_t acc[2][8][4];

    #pragma unroll 1
    for (int q = 0; q < NQ; q++) {
        CP_WAIT(1);                 // A + B_q complete; B_{q+1} may be in flight
        __syncthreads();

        if (q + 2 < NQ) issue_B(q + 2);   // stage (q+2)%3 was consumed at q-1

        if ((q & 3) == 0) {
            #pragma unroll
            for (int i = 0; i < 2; i++)
                #pragma unroll
                for (int j = 0; j < 8; j++)
                    #pragma unroll
                    for (int k = 0; k < 4; k++) acc[i][j][k] = 0;
        }

        const uint32_t a_base = a_region + (q & 3) * B_STAGE;
        const uint32_t b_base = b_region + (q % 3) * B_STAGE;

        #pragma unroll
        for (int ks = 0; ks < 4; ks++) {
            uint32_t a[2][4];
            #pragma unroll
            for (int i = 0; i < 2; i++) {
                const uint32_t off =
                    swz((uint32_t)((a_row_l + i * 16) * 128 + ks * 32 + a_kb_l));
                ldmatrix_x4(a[i][0], a[i][1], a[i][2], a[i][3], a_base + off);
            }
            uint32_t b[4][4];
            #pragma unroll
            for (int j2 = 0; j2 < 4; j2++) {
                const uint32_t off =
                    swz((uint32_t)((b_n_l + j2 * 16) * 128 + ks * 32 + b_kb_l));
                ldmatrix_x4(b[j2][0], b[j2][1], b[j2][2], b[j2][3], b_base + off);
            }
            #pragma unroll
            for (int i = 0; i < 2; i++)
                #pragma unroll
                for (int j = 0; j < 8; j++) {
                    const int j2 = j >> 1, h = j & 1;
                    mma_s8(acc[i][j], a[i][0], a[i][1], a[i][2], a[i][3],
                           b[j2][2 * h], b[j2][2 * h + 1]);
                }
        }

        if ((q & 3) == 3) {
            // screen this tn tile: flag rows whose head Q-dot could exceed bound
            #pragma unroll
            for (int i = 0; i < 2; i++) {
                #pragma unroll
                for (int h = 0; h < 2; h++) {
                    int f = 0;
                    #pragma unroll
                    for (int j = 0; j < 8; j++)
                        f |= (acc[i][j][2 * h] > thr) | (acc[i][j][2 * h + 1] > thr);
                    f |= __shfl_xor_sync(0xFFFFFFFFu, f, 1);
                    f |= __shfl_xor_sync(0xFFFFFFFFu, f, 2);
                    if ((lid & 3) == 0 && f) {
                        const int row = tm * BM_ + warp_m * 32 + i * 16 + h * 8 + (lid >> 2);
                        g_flag[row] = 1;   // benign race
                    }
                }
            }
        }
    }
}

// ---------------------------------------------------------------------------
// K3: exact fp32 fallback for flagged rows (normally zero rows).
// 256 blocks; each scans 32 rows, processes flagged ones (uniform branch).
// ---------------------------------------------------------------------------
__global__ void __launch_bounds__(256) rqa_fallback(
    const float* __restrict__ Ex, const float* __restrict__ Ey,
    float* __restrict__ out)
{
    __shared__ float xs[DIMS];
    __shared__ float ws[8];
    const int tid = threadIdx.x;

    #pragma unroll 1
    for (int r = 0; r < 32; r++) {
        const int row = blockIdx.x * 32 + r;
        if (g_flag[row] == 0) continue;          // uniform per block

        float4 v = reinterpret_cast<const float4*>(Ex)[(size_t)row * 256 + tid];
        float ss = blk_sum(v.x * v.x + v.y * v.y + v.z * v.z + v.w * v.w, ws, tid);
        xs[tid * 4 + 0] = v.x; xs[tid * 4 + 1] = v.y;
        xs[tid * 4 + 2] = v.z; xs[tid * 4 + 3] = v.w;
        __syncthreads();
        const float nx = fmaxf(sqrtf(ss), 1e-8f);

        int any = 0;
        for (int m = tid; m < NROWS; m += 256) {
            const float* y = Ey + (size_t)m * DIMS;
            float dot = 0.0f, ssy = 0.0f;
            #pragma unroll 4
            for (int k = 0; k < DIMS; k++) {
                float yv = y[k];
                dot += xs[k] * yv;
                ssy += yv * yv;
            }
            float ny = fmaxf(sqrtf(ssy), 1e-8f);
            if (dot > 0.9f * nx * ny) any = 1;
        }
        if (any) out[row] = 1.0f;
        __syncthreads();                         // xs reuse safety
    }
}

// ---------------------------------------------------------------------------
// Launch
// ---------------------------------------------------------------------------
extern "C" void kernel_launch(void* const* d_in, const int* in_sizes, int n_in,
                              void* d_out, int out_size)
{
    const float* Ex = (const float*)d_in[0];
    const float* Ey = (const float*)d_in[1];
    float* out = (float*)d_out;

    cudaFuncSetAttribute(rqa_gemm, cudaFuncAttributeMaxDynamicSharedMemorySize, SMEM_DYN);

    rqa_init<<<1, 32>>>();
    rqa_normalize<<<NROWS, 256>>>(Ex, Ey, out);
    dim3 grid(NROWS / BM_, NROWS / (BN_ * NSPLIT));
    rqa_gemm<<<grid, GT_, SMEM_DYN>>>();
    rqa_fallback<<<256, 256>>>(Ex, Ey, out);
}